// round 8
// baseline (speedup 1.0000x reference)
#include <cuda_runtime.h>
#include <math.h>
#include <stdint.h>

#define NB    8
#define NPTS  4096
#define BN    32768
#define NEDGE 524288
#define C0    64
#define C1    128
#define C2    512

// ---------------- scratch ----------------
__device__ float g_h0[BN * C0];      // hs0 = dinv * h0
__device__ float g_agg0[BN * C0];    // seeded with hs0 (self loop), edges add
__device__ float g_h1[BN * C1];
__device__ float g_agg1[BN * C1];
__device__ float g_dinv[BN];
__device__ int   g_deg[BN];
__device__ float g_lat[NB * C2];
__device__ float g_lat2[NB * C2];
__device__ float g_base[NB * 6];

__device__ __forceinline__ float selu_f(float v) {
    const float scale = 1.0507009873554805f;
    const float alpha = 1.6732632423543772f;
    return v > 0.0f ? scale * v : scale * alpha * expm1f(v);
}

__device__ __forceinline__ void atomicMaxF(float* addr, float v) {
    if (v >= 0.0f) atomicMax((int*)addr, __float_as_int(v));
    else           atomicMin((unsigned int*)addr, __float_as_uint(v));
}

__device__ __forceinline__ void red_add_v4(float* p, float4 v) {
    asm volatile("red.global.add.v4.f32 [%0], {%1,%2,%3,%4};"
                 :: "l"(p), "f"(v.x), "f"(v.y), "f"(v.z), "f"(v.w) : "memory");
}

__device__ __forceinline__ float f2tf32f(float v) {
    uint32_t r;
    asm("cvt.rna.tf32.f32 %0, %1;" : "=r"(r) : "f"(v));
    return __uint_as_float(r);
}

__device__ __forceinline__ float4 ldg_nc4(const float4* p) {
    float4 v;
    asm volatile("ld.global.nc.v4.f32 {%0,%1,%2,%3}, [%4];"
                 : "=f"(v.x), "=f"(v.y), "=f"(v.z), "=f"(v.w) : "l"(p));
    return v;
}

__device__ __forceinline__ void mma_tf32(float d[4],
                                         uint32_t a0, uint32_t a1, uint32_t a2, uint32_t a3,
                                         uint32_t b0, uint32_t b1) {
    asm volatile("mma.sync.aligned.m16n8k8.row.col.f32.tf32.tf32.f32 "
                 "{%0,%1,%2,%3},{%4,%5,%6,%7},{%8,%9},{%0,%1,%2,%3};"
                 : "+f"(d[0]), "+f"(d[1]), "+f"(d[2]), "+f"(d[3])
                 : "r"(a0), "r"(a1), "r"(a2), "r"(a3), "r"(b0), "r"(b1));
}

// ---------------- init / degree ----------------
__global__ void init_kernel() {
    int i = blockIdx.x * blockDim.x + threadIdx.x;
    if (i < BN) g_deg[i] = 1;
    if (i < NB * C2) g_lat[i] = __int_as_float(0xff800000);
}
__global__ void deg_kernel(const int* __restrict__ dst) {
    int e = blockIdx.x * blockDim.x + threadIdx.x;
    if (e < NEDGE) atomicAdd(&g_deg[dst[e]], 1);
}
__global__ void dinv_kernel() {
    int i = blockIdx.x * blockDim.x + threadIdx.x;
    if (i < BN) g_dinv[i] = rsqrtf((float)g_deg[i]);
}

// ---------------- cov + 12->64 + selu -> hs0 (writes h0 AND agg0) ----------------
// 256 threads, 64 points per block; interior blocks take a predicate-free fast path.
__global__ void __launch_bounds__(256)
cov_e1_kernel(const float* __restrict__ x,
              const float* __restrict__ w_e1,
              const float* __restrict__ b_e1) {
    __shared__ float xw[88][3];
    __shared__ float ws[12 * 64];
    __shared__ float bs[64];
    __shared__ float feat_s[64][13];
    __shared__ float out_s[64][68];
    int t = threadIdx.x;
    int blk = blockIdx.x;
    int b = blk >> 6;                 // 64 blocks per batch
    int n_base = (blk & 63) << 6;     // batch-local start (64 points)
    int point0 = blk << 6;

    if (t < 88) {
        int idx = n_base + t - 12;
        idx = min(max(idx, 0), NPTS - 1);
        const float* xp = x + (((size_t)b << 12) + idx) * 3;
        xw[t][0] = xp[0]; xw[t][1] = xp[1]; xw[t][2] = xp[2];
    }
    for (int i = t; i < 12 * 64; i += 256) ws[i] = w_e1[i];
    if (t < 64) bs[t] = b_e1[t];
    __syncthreads();

    if (t < 64) {
        int n = n_base + t;
        bool interior = (n >= 12) && (n + 12 < NPTS);
        float m0 = 0.f, m1 = 0.f, m2 = 0.f;
        float c00=0,c01=0,c02=0,c11=0,c12=0,c22=0;
        float invn1;
        if (interior) {
            #pragma unroll
            for (int w = 0; w < 25; w++) {
                m0 += xw[t + w][0]; m1 += xw[t + w][1]; m2 += xw[t + w][2];
            }
            const float ic = 1.0f / 25.0f;
            m0 *= ic; m1 *= ic; m2 *= ic;
            #pragma unroll
            for (int w = 0; w < 25; w++) {
                float d0 = xw[t + w][0] - m0;
                float d1 = xw[t + w][1] - m1;
                float d2 = xw[t + w][2] - m2;
                c00 = fmaf(d0,d0,c00); c01 = fmaf(d0,d1,c01); c02 = fmaf(d0,d2,c02);
                c11 = fmaf(d1,d1,c11); c12 = fmaf(d1,d2,c12); c22 = fmaf(d2,d2,c22);
            }
            invn1 = 1.0f / 23.0f;
        } else {
            float cnt = 0.f;
            #pragma unroll
            for (int w = 0; w < 25; w++) {
                int nn = n + w - 12;
                if (nn >= 0 && nn < NPTS) {
                    m0 += xw[t + w][0]; m1 += xw[t + w][1]; m2 += xw[t + w][2];
                    cnt += 1.0f;
                }
            }
            float ic = 1.0f / cnt;
            m0 *= ic; m1 *= ic; m2 *= ic;
            #pragma unroll
            for (int w = 0; w < 25; w++) {
                int nn = n + w - 12;
                if (nn >= 0 && nn < NPTS) {
                    float d0 = xw[t + w][0] - m0;
                    float d1 = xw[t + w][1] - m1;
                    float d2 = xw[t + w][2] - m2;
                    c00 = fmaf(d0,d0,c00); c01 = fmaf(d0,d1,c01); c02 = fmaf(d0,d2,c02);
                    c11 = fmaf(d1,d1,c11); c12 = fmaf(d1,d2,c12); c22 = fmaf(d2,d2,c22);
                }
            }
            invn1 = 1.0f / 23.0f;
        }
        feat_s[t][0] = xw[t + 12][0]; feat_s[t][1] = xw[t + 12][1]; feat_s[t][2] = xw[t + 12][2];
        feat_s[t][3] = c00 * invn1; feat_s[t][4]  = c01 * invn1; feat_s[t][5]  = c02 * invn1;
        feat_s[t][6] = c01 * invn1; feat_s[t][7]  = c11 * invn1; feat_s[t][8]  = c12 * invn1;
        feat_s[t][9] = c02 * invn1; feat_s[t][10] = c12 * invn1; feat_s[t][11] = c22 * invn1;
    }
    __syncthreads();

    int pt = t >> 2, quarter = t & 3;     // 4 threads per point, 16 cols each
    float dv = g_dinv[point0 + pt];
    float feat[12];
    #pragma unroll
    for (int k = 0; k < 12; k++) feat[k] = feat_s[pt][k];
    #pragma unroll
    for (int jj = 0; jj < 16; jj++) {
        int j = (quarter << 4) + jj;
        float acc = bs[j];
        #pragma unroll
        for (int k = 0; k < 12; k++) acc = fmaf(feat[k], ws[k * 64 + j], acc);
        out_s[pt][j] = dv * selu_f(acc);
    }
    __syncthreads();

    for (int i = t; i < 1024; i += 256) {   // 64 rows x 16 float4
        int row = i >> 4, q = i & 15;
        float4 v = *reinterpret_cast<const float4*>(&out_s[row][q << 2]);
        size_t gaddr = (size_t)(point0 + row) * 64 + (q << 2);
        *reinterpret_cast<float4*>(g_h0 + gaddr)   = v;
        *reinterpret_cast<float4*>(g_agg0 + gaddr) = v;
    }
}

// ---------------- edge scatter, 32B-granular: agg[d] += hs[s] ----------------
// LOGC = log2(#32B chunks per row). Each thread handles one 32B chunk:
// two float4 loads + two v4 REDs hitting the same L2 sector.
template<int LOGC>
__global__ void edge_kernel(const int* __restrict__ src, const int* __restrict__ dst,
                            const float* __restrict__ hs, float* __restrict__ agg) {
    int idx = blockIdx.x * blockDim.x + threadIdx.x;
    int e = idx >> LOGC;
    int g = idx & ((1 << LOGC) - 1);
    if (e >= NEDGE) return;
    int s = src[e], d = dst[e];
    const float4* ps = reinterpret_cast<const float4*>(hs) + (((size_t)s) << (LOGC + 1)) + (g << 1);
    float4 v0 = ldg_nc4(ps);
    float4 v1 = ldg_nc4(ps + 1);
    float* pd = agg + (((size_t)d) << (LOGC + 3)) + (g << 3);
    red_add_v4(pd, v0);
    red_add_v4(pd + 4, v1);
}

// ---------------- single-pass TF32 GEMM, 128x128 tile, double-buffered ----------------
template<int N, int K, bool DO_MAX>
__global__ void __launch_bounds__(256, 2)
gemm_tf32_kernel(const float* __restrict__ A, const float* __restrict__ dinv,
                 const float* __restrict__ Wt, const float* __restrict__ bias,
                 float* __restrict__ O1, float* __restrict__ O2,
                 float* __restrict__ lat) {
    __shared__ float Ah[2][128][20];
    __shared__ float Bh[2][16][132];

    int tid = threadIdx.x;
    int warp = tid >> 5, lane = tid & 31;
    int wm = warp >> 2, wn = warp & 3;
    int g = lane >> 2, c = lane & 3;
    int row0 = blockIdx.y * 128, col0 = blockIdx.x * 128;

    int ar = tid >> 1;
    int ak = (tid & 1) << 3;
    float dv = dinv[row0 + ar];
    int bkr = tid >> 4;
    int bc0 = (tid & 15) << 3;

    const int KT = K / 16;

    float d[4][4][4];
    #pragma unroll
    for (int mt = 0; mt < 4; mt++)
        #pragma unroll
        for (int nt = 0; nt < 4; nt++)
            #pragma unroll
            for (int r = 0; r < 4; r++) d[mt][nt][r] = 0.0f;

    {
        float4 a0 = *reinterpret_cast<const float4*>(A + (size_t)(row0 + ar) * K + ak);
        float4 a1 = *reinterpret_cast<const float4*>(A + (size_t)(row0 + ar) * K + ak + 4);
        Ah[0][ar][ak + 0] = f2tf32f(dv * a0.x); Ah[0][ar][ak + 1] = f2tf32f(dv * a0.y);
        Ah[0][ar][ak + 2] = f2tf32f(dv * a0.z); Ah[0][ar][ak + 3] = f2tf32f(dv * a0.w);
        Ah[0][ar][ak + 4] = f2tf32f(dv * a1.x); Ah[0][ar][ak + 5] = f2tf32f(dv * a1.y);
        Ah[0][ar][ak + 6] = f2tf32f(dv * a1.z); Ah[0][ar][ak + 7] = f2tf32f(dv * a1.w);
        float4 b0 = *reinterpret_cast<const float4*>(Wt + (size_t)bkr * N + col0 + bc0);
        float4 b1 = *reinterpret_cast<const float4*>(Wt + (size_t)bkr * N + col0 + bc0 + 4);
        Bh[0][bkr][bc0 + 0] = f2tf32f(b0.x); Bh[0][bkr][bc0 + 1] = f2tf32f(b0.y);
        Bh[0][bkr][bc0 + 2] = f2tf32f(b0.z); Bh[0][bkr][bc0 + 3] = f2tf32f(b0.w);
        Bh[0][bkr][bc0 + 4] = f2tf32f(b1.x); Bh[0][bkr][bc0 + 5] = f2tf32f(b1.y);
        Bh[0][bkr][bc0 + 6] = f2tf32f(b1.z); Bh[0][bkr][bc0 + 7] = f2tf32f(b1.w);
    }
    __syncthreads();

    for (int kt = 0; kt < KT; kt++) {
        int cur = kt & 1, nxt = cur ^ 1;
        float4 a0, a1, b0, b1;
        bool more = (kt + 1 < KT);
        if (more) {
            int koff = (kt + 1) * 16;
            a0 = *reinterpret_cast<const float4*>(A + (size_t)(row0 + ar) * K + koff + ak);
            a1 = *reinterpret_cast<const float4*>(A + (size_t)(row0 + ar) * K + koff + ak + 4);
            b0 = *reinterpret_cast<const float4*>(Wt + (size_t)(koff + bkr) * N + col0 + bc0);
            b1 = *reinterpret_cast<const float4*>(Wt + (size_t)(koff + bkr) * N + col0 + bc0 + 4);
        }

        #pragma unroll
        for (int ks = 0; ks < 2; ks++) {
            int k0 = ks << 3;
            uint32_t af[4][4];
            #pragma unroll
            for (int mt = 0; mt < 4; mt++) {
                int rm = wm * 64 + mt * 16;
                af[mt][0] = __float_as_uint(Ah[cur][rm + g][k0 + c]);
                af[mt][1] = __float_as_uint(Ah[cur][rm + g + 8][k0 + c]);
                af[mt][2] = __float_as_uint(Ah[cur][rm + g][k0 + c + 4]);
                af[mt][3] = __float_as_uint(Ah[cur][rm + g + 8][k0 + c + 4]);
            }
            uint32_t bf[4][2];
            #pragma unroll
            for (int nt = 0; nt < 4; nt++) {
                int nb = wn * 32 + nt * 8;
                bf[nt][0] = __float_as_uint(Bh[cur][k0 + c][nb + g]);
                bf[nt][1] = __float_as_uint(Bh[cur][k0 + c + 4][nb + g]);
            }
            #pragma unroll
            for (int mt = 0; mt < 4; mt++)
                #pragma unroll
                for (int nt = 0; nt < 4; nt++)
                    mma_tf32(d[mt][nt], af[mt][0], af[mt][1], af[mt][2], af[mt][3],
                             bf[nt][0], bf[nt][1]);
        }

        if (more) {
            Ah[nxt][ar][ak + 0] = f2tf32f(dv * a0.x); Ah[nxt][ar][ak + 1] = f2tf32f(dv * a0.y);
            Ah[nxt][ar][ak + 2] = f2tf32f(dv * a0.z); Ah[nxt][ar][ak + 3] = f2tf32f(dv * a0.w);
            Ah[nxt][ar][ak + 4] = f2tf32f(dv * a1.x); Ah[nxt][ar][ak + 5] = f2tf32f(dv * a1.y);
            Ah[nxt][ar][ak + 6] = f2tf32f(dv * a1.z); Ah[nxt][ar][ak + 7] = f2tf32f(dv * a1.w);
            Bh[nxt][bkr][bc0 + 0] = f2tf32f(b0.x); Bh[nxt][bkr][bc0 + 1] = f2tf32f(b0.y);
            Bh[nxt][bkr][bc0 + 2] = f2tf32f(b0.z); Bh[nxt][bkr][bc0 + 3] = f2tf32f(b0.w);
            Bh[nxt][bkr][bc0 + 4] = f2tf32f(b1.x); Bh[nxt][bkr][bc0 + 5] = f2tf32f(b1.y);
            Bh[nxt][bkr][bc0 + 6] = f2tf32f(b1.z); Bh[nxt][bkr][bc0 + 7] = f2tf32f(b1.w);
        }
        __syncthreads();
    }

    float bv[4][2];
    #pragma unroll
    for (int nt = 0; nt < 4; nt++) {
        int cc = col0 + wn * 32 + nt * 8 + (c << 1);
        bv[nt][0] = bias[cc];
        bv[nt][1] = bias[cc + 1];
    }

    if (!DO_MAX) {
        #pragma unroll
        for (int mt = 0; mt < 4; mt++) {
            int rbase = row0 + wm * 64 + mt * 16;
            #pragma unroll
            for (int half = 0; half < 2; half++) {
                int r = rbase + g + half * 8;
                float dv2 = dinv[r];
                #pragma unroll
                for (int nt = 0; nt < 4; nt++) {
                    int cc = col0 + wn * 32 + nt * 8 + (c << 1);
                    float2 o;
                    o.x = dv2 * selu_f(d[mt][nt][half * 2 + 0] + bv[nt][0]);
                    o.y = dv2 * selu_f(d[mt][nt][half * 2 + 1] + bv[nt][1]);
                    size_t addr = (size_t)r * N + cc;
                    *reinterpret_cast<float2*>(O1 + addr) = o;
                    *reinterpret_cast<float2*>(O2 + addr) = o;
                }
            }
        }
    } else {
        float mv[4][2];
        #pragma unroll
        for (int nt = 0; nt < 4; nt++) { mv[nt][0] = mv[nt][1] = __int_as_float(0xff800000); }
        #pragma unroll
        for (int mt = 0; mt < 4; mt++)
            #pragma unroll
            for (int nt = 0; nt < 4; nt++) {
                mv[nt][0] = fmaxf(mv[nt][0], fmaxf(selu_f(d[mt][nt][0] + bv[nt][0]),
                                                   selu_f(d[mt][nt][2] + bv[nt][0])));
                mv[nt][1] = fmaxf(mv[nt][1], fmaxf(selu_f(d[mt][nt][1] + bv[nt][1]),
                                                   selu_f(d[mt][nt][3] + bv[nt][1])));
            }
        #pragma unroll
        for (int off = 4; off <= 16; off <<= 1)
            #pragma unroll
            for (int nt = 0; nt < 4; nt++) {
                mv[nt][0] = fmaxf(mv[nt][0], __shfl_xor_sync(0xffffffffu, mv[nt][0], off));
                mv[nt][1] = fmaxf(mv[nt][1], __shfl_xor_sync(0xffffffffu, mv[nt][1], off));
            }
        if (lane < 4) {
            int b = row0 >> 12;
            #pragma unroll
            for (int nt = 0; nt < 4; nt++) {
                int cc = col0 + wn * 32 + nt * 8 + (lane << 1);
                atomicMaxF(&lat[b * C2 + cc], mv[nt][0]);
                atomicMaxF(&lat[b * C2 + cc + 1], mv[nt][1]);
            }
        }
    }
}

// ---------------- lat2 = selu(lat @ w_e2 + b_e2) ----------------
__global__ void e2_kernel(const float* __restrict__ lat, const float* __restrict__ w,
                          const float* __restrict__ bias, float* __restrict__ lat2) {
    __shared__ float row[C2];
    int c = threadIdx.x;
    row[c] = lat[blockIdx.x * C2 + c];
    __syncthreads();
    float acc = bias[c];
    #pragma unroll 8
    for (int k = 0; k < C2; k++) acc = fmaf(row[k], w[k * C2 + c], acc);
    lat2[blockIdx.x * C2 + c] = selu_f(acc);
}

// ---------------- decoder ----------------
__global__ void base_kernel(const float* __restrict__ lat2,
                            const float* __restrict__ w_d1,
                            const float* __restrict__ w_d2,
                            float* __restrict__ base) {
    int o = blockIdx.x;
    int b = o / 6, t = o % 6, j = t % 3;
    const float* w = (t < 3) ? w_d1 : w_d2;
    int lane = threadIdx.x;
    float s = 0.0f;
    for (int c = lane; c < C2; c += 32) s += lat2[b * C2 + c] * w[c * 3 + j];
    #pragma unroll
    for (int off = 16; off > 0; off >>= 1) s += __shfl_xor_sync(0xffffffffu, s, off);
    if (lane == 0) base[b * 6 + t] = s;
}

__global__ void final_kernel(const float* __restrict__ base,
                             const float* __restrict__ w_d1, const float* __restrict__ b_d1,
                             const float* __restrict__ w_d2, const float* __restrict__ b_d2,
                             float* __restrict__ out) {
    int idx = blockIdx.x * blockDim.x + threadIdx.x;
    int b = idx >> 12, n = idx & 4095;
    int ix = n / 46, iy = n % 46;
    float y0 = 1.0f + ix * (119.0f / 90.0f);
    float y1 = 1.0f + iy * (59.0f / 45.0f);
    float kk[3];
    #pragma unroll
    for (int j = 0; j < 3; j++)
        kk[j] = selu_f(base[b * 6 + j] + y0 * w_d1[512 * 3 + j] + y1 * w_d1[513 * 3 + j] + b_d1[j]);
    #pragma unroll
    for (int j = 0; j < 3; j++) {
        float v = base[b * 6 + 3 + j]
                + kk[0] * w_d2[512 * 3 + j]
                + kk[1] * w_d2[513 * 3 + j]
                + kk[2] * w_d2[514 * 3 + j]
                + b_d2[j];
        out[(size_t)idx * 3 + j] = selu_f(v);
    }
}

// ---------------- launch ----------------
extern "C" void kernel_launch(void* const* d_in, const int* in_sizes, int n_in,
                              void* d_out, int out_size) {
    const float* x    = (const float*)d_in[0];
    const int*   knn  = (const int*)  d_in[1];
    const float* w_e1 = (const float*)d_in[2];
    const float* b_e1 = (const float*)d_in[3];
    const float* w_g1 = (const float*)d_in[4];
    const float* b_g1 = (const float*)d_in[5];
    const float* w_g2 = (const float*)d_in[6];
    const float* b_g2 = (const float*)d_in[7];
    const float* w_e2 = (const float*)d_in[8];
    const float* b_e2 = (const float*)d_in[9];
    const float* w_d1 = (const float*)d_in[10];
    const float* b_d1 = (const float*)d_in[11];
    const float* w_d2 = (const float*)d_in[12];
    const float* b_d2 = (const float*)d_in[13];
    float* out = (float*)d_out;
    const int* src = knn;
    const int* dst = knn + NEDGE;

    float *p_h0, *p_agg0, *p_h1, *p_agg1, *p_lat, *p_lat2, *p_base, *p_dinv;
    cudaGetSymbolAddress((void**)&p_h0,   g_h0);
    cudaGetSymbolAddress((void**)&p_agg0, g_agg0);
    cudaGetSymbolAddress((void**)&p_h1,   g_h1);
    cudaGetSymbolAddress((void**)&p_agg1, g_agg1);
    cudaGetSymbolAddress((void**)&p_lat,  g_lat);
    cudaGetSymbolAddress((void**)&p_lat2, g_lat2);
    cudaGetSymbolAddress((void**)&p_base, g_base);
    cudaGetSymbolAddress((void**)&p_dinv, g_dinv);

    init_kernel<<<BN / 256, 256>>>();
    deg_kernel<<<NEDGE / 256, 256>>>(dst);
    dinv_kernel<<<BN / 256, 256>>>();
    cov_e1_kernel<<<BN / 64, 256>>>(x, w_e1, b_e1);

    // GCN layer 1: 8 chunks of 32B per row (64 floats)
    edge_kernel<3><<<(NEDGE * 8) / 256, 256>>>(src, dst, p_h0, p_agg0);
    gemm_tf32_kernel<C1, C0, false><<<dim3(C1 / 128, BN / 128), 256>>>(
        p_agg0, p_dinv, w_g1, b_g1, p_h1, p_agg1, nullptr);

    // GCN layer 2 + fused max-pool: 16 chunks of 32B per row (128 floats)
    edge_kernel<4><<<(NEDGE * 16) / 256, 256>>>(src, dst, p_h1, p_agg1);
    gemm_tf32_kernel<C2, C1, true><<<dim3(C2 / 128, BN / 128), 256>>>(
        p_agg1, p_dinv, w_g2, b_g2, nullptr, nullptr, p_lat);

    e2_kernel<<<NB, C2>>>(p_lat, w_e2, b_e2, p_lat2);
    base_kernel<<<NB * 6, 32>>>(p_lat2, w_d1, w_d2, p_base);
    final_kernel<<<BN / 256, 256>>>(p_base, w_d1, b_d1, w_d2, b_d2, out);
}

// round 11
// speedup vs baseline: 1.4184x; 1.4184x over previous
#include <cuda_runtime.h>
#include <cuda_fp16.h>
#include <math.h>
#include <stdint.h>

#define NB    8
#define NPTS  4096
#define BN    32768
#define NEDGE 524288
#define C0    64
#define C1    128
#define C2    512

// ---------------- scratch ----------------
__device__ __half g_h0[BN * C0];     // hs0 = dinv*h0, fp16 payload
__device__ __half g_agg0[BN * C0];   // seeded with hs0, edges RED-add fp16
__device__ __half g_h1[BN * C1];
__device__ __half g_agg1[BN * C1];
__device__ float  g_dinv[BN];
__device__ int    g_deg[BN];
__device__ float  g_lat[NB * C2];
__device__ float  g_lat2[NB * C2];
__device__ float  g_base[NB * 6];

__device__ __forceinline__ float selu_f(float v) {
    const float scale = 1.0507009873554805f;
    const float alpha = 1.6732632423543772f;
    return v > 0.0f ? scale * v : scale * alpha * expm1f(v);
}

__device__ __forceinline__ void atomicMaxF(float* addr, float v) {
    if (v >= 0.0f) atomicMax((int*)addr, __float_as_int(v));
    else           atomicMin((unsigned int*)addr, __float_as_uint(v));
}

__device__ __forceinline__ float f2tf32f(float v) {
    uint32_t r;
    asm("cvt.rna.tf32.f32 %0, %1;" : "=r"(r) : "f"(v));
    return __uint_as_float(r);
}

__device__ __forceinline__ uint32_t h2_bits(__half2 h) {
    uint32_t u;
    *reinterpret_cast<__half2*>(&u) = h;
    return u;
}
__device__ __forceinline__ __half2 bits_h2(uint32_t u) {
    return *reinterpret_cast<__half2*>(&u);
}

__device__ __forceinline__ uint4 ldg_nc_u4(const uint4* p) {
    uint4 v;
    asm volatile("ld.global.nc.v4.u32 {%0,%1,%2,%3}, [%4];"
                 : "=r"(v.x), "=r"(v.y), "=r"(v.z), "=r"(v.w) : "l"(p));
    return v;
}

// 16B fp16 vector reduction: 8 halves per instruction
__device__ __forceinline__ void red_add_v4h(__half* p, uint4 v) {
    asm volatile("red.global.add.noftz.v4.f16x2 [%0], {%1,%2,%3,%4};"
                 :: "l"(p), "r"(v.x), "r"(v.y), "r"(v.z), "r"(v.w) : "memory");
}

__device__ __forceinline__ void mma_tf32(float d[4],
                                         uint32_t a0, uint32_t a1, uint32_t a2, uint32_t a3,
                                         uint32_t b0, uint32_t b1) {
    asm volatile("mma.sync.aligned.m16n8k8.row.col.f32.tf32.tf32.f32 "
                 "{%0,%1,%2,%3},{%4,%5,%6,%7},{%8,%9},{%0,%1,%2,%3};"
                 : "+f"(d[0]), "+f"(d[1]), "+f"(d[2]), "+f"(d[3])
                 : "r"(a0), "r"(a1), "r"(a2), "r"(a3), "r"(b0), "r"(b1));
}

// ---------------- init / degree ----------------
__global__ void init_kernel() {
    int i = blockIdx.x * blockDim.x + threadIdx.x;
    if (i < BN) g_deg[i] = 1;
    if (i < NB * C2) g_lat[i] = __int_as_float(0xff800000);
}
__global__ void deg_kernel(const int* __restrict__ dst) {
    int e = blockIdx.x * blockDim.x + threadIdx.x;
    if (e < NEDGE) atomicAdd(&g_deg[dst[e]], 1);
}
__global__ void dinv_kernel() {
    int i = blockIdx.x * blockDim.x + threadIdx.x;
    if (i < BN) g_dinv[i] = rsqrtf((float)g_deg[i]);
}

// ---------------- cov + 12->64 + selu -> hs0 fp16 (writes h0 AND agg0) ----------------
// 128 threads, 32 points per block (R7 shape).
__global__ void __launch_bounds__(128)
cov_e1_kernel(const float* __restrict__ x,
              const float* __restrict__ w_e1,
              const float* __restrict__ b_e1) {
    __shared__ float xw[56][3];
    __shared__ float ws[12 * 64];
    __shared__ float bs[64];
    __shared__ float feat_s[32][13];
    __shared__ float out_s[32][68];
    int t = threadIdx.x;
    int blk = blockIdx.x;
    int b = blk >> 7;
    int n_base = (blk & 127) << 5;
    int point0 = blk << 5;

    if (t < 56) {
        int idx = n_base + t - 12;
        idx = min(max(idx, 0), NPTS - 1);
        const float* xp = x + (((size_t)b << 12) + idx) * 3;
        xw[t][0] = xp[0]; xw[t][1] = xp[1]; xw[t][2] = xp[2];
    }
    for (int i = t; i < 12 * 64; i += 128) ws[i] = w_e1[i];
    if (t < 64) bs[t] = b_e1[t];
    __syncthreads();

    if (t < 32) {
        int n = n_base + t;
        float m0 = 0.f, m1 = 0.f, m2 = 0.f, cnt = 0.f;
        #pragma unroll
        for (int w = 0; w < 25; w++) {
            int nn = n + w - 12;
            if (nn >= 0 && nn < NPTS) {
                m0 += xw[t + w][0]; m1 += xw[t + w][1]; m2 += xw[t + w][2];
                cnt += 1.0f;
            }
        }
        float ic = 1.0f / cnt;
        m0 *= ic; m1 *= ic; m2 *= ic;
        float c00=0,c01=0,c02=0,c11=0,c12=0,c22=0;
        #pragma unroll
        for (int w = 0; w < 25; w++) {
            int nn = n + w - 12;
            if (nn >= 0 && nn < NPTS) {
                float d0 = xw[t + w][0] - m0;
                float d1 = xw[t + w][1] - m1;
                float d2 = xw[t + w][2] - m2;
                c00 = fmaf(d0,d0,c00); c01 = fmaf(d0,d1,c01); c02 = fmaf(d0,d2,c02);
                c11 = fmaf(d1,d1,c11); c12 = fmaf(d1,d2,c12); c22 = fmaf(d2,d2,c22);
            }
        }
        const float s = 1.0f / 23.0f;
        feat_s[t][0] = xw[t + 12][0]; feat_s[t][1] = xw[t + 12][1]; feat_s[t][2] = xw[t + 12][2];
        feat_s[t][3] = c00 * s; feat_s[t][4]  = c01 * s; feat_s[t][5]  = c02 * s;
        feat_s[t][6] = c01 * s; feat_s[t][7]  = c11 * s; feat_s[t][8]  = c12 * s;
        feat_s[t][9] = c02 * s; feat_s[t][10] = c12 * s; feat_s[t][11] = c22 * s;
    }
    __syncthreads();

    int pt = t >> 2, quarter = t & 3;     // 4 threads per point, 16 cols each
    float dv = g_dinv[point0 + pt];
    float feat[12];
    #pragma unroll
    for (int k = 0; k < 12; k++) feat[k] = feat_s[pt][k];
    #pragma unroll
    for (int jj = 0; jj < 16; jj++) {
        int j = (quarter << 4) + jj;
        float acc = bs[j];
        #pragma unroll
        for (int k = 0; k < 12; k++) acc = fmaf(feat[k], ws[k * 64 + j], acc);
        out_s[pt][j] = dv * selu_f(acc);
    }
    __syncthreads();

    // write fp16: 32 rows x 64 halves; each i handles 8 floats -> uint4
    for (int i = t; i < 256; i += 128) {
        int row = i >> 3, seg = i & 7;
        const float* src = &out_s[row][seg << 3];
        uint4 pk;
        pk.x = h2_bits(__floats2half2_rn(src[0], src[1]));
        pk.y = h2_bits(__floats2half2_rn(src[2], src[3]));
        pk.z = h2_bits(__floats2half2_rn(src[4], src[5]));
        pk.w = h2_bits(__floats2half2_rn(src[6], src[7]));
        size_t goff = (size_t)(point0 + row) * 64 + (seg << 3);
        *reinterpret_cast<uint4*>(g_h0 + goff)   = pk;
        *reinterpret_cast<uint4*>(g_agg0 + goff) = pk;
    }
}

// ---------------- edge scatter fp16: agg[d] += hs[s] ----------------
// Chunk = 8 halves (16B). LOGC = log2(chunks per row); row halves = 8<<LOGC.
// src offset: uint4 units (8 halves); dst offset: halves (g<<3). Consistent.
template<int LOGC>
__global__ void edge_kernel(const int* __restrict__ src, const int* __restrict__ dst,
                            const __half* __restrict__ hs, __half* __restrict__ agg) {
    int idx = blockIdx.x * blockDim.x + threadIdx.x;
    int e = idx >> LOGC;
    int g = idx & ((1 << LOGC) - 1);
    if (e >= NEDGE) return;
    int s = src[e], d = dst[e];
    uint4 v = ldg_nc_u4(reinterpret_cast<const uint4*>(hs + ((size_t)s << (LOGC + 3))) + g);
    red_add_v4h(agg + ((size_t)d << (LOGC + 3)) + (g << 3), v);
}

// ---------------- single-pass TF32 GEMM, fp16 A operand, 128x128 tile, double-buffered ----------------
// out = selu( (dinv[row]*Ah16[row]) @ W + bias ); !DO_MAX writes fp16 to O1,O2; DO_MAX -> lat f32.
template<int N, int K, bool DO_MAX>
__global__ void __launch_bounds__(256, 2)
gemm_tf32_kernel(const __half* __restrict__ A, const float* __restrict__ dinv,
                 const float* __restrict__ Wt, const float* __restrict__ bias,
                 __half* __restrict__ O1, __half* __restrict__ O2,
                 float* __restrict__ lat) {
    __shared__ float Ah[2][128][20];
    __shared__ float Bh[2][16][132];

    int tid = threadIdx.x;
    int warp = tid >> 5, lane = tid & 31;
    int wm = warp >> 2, wn = warp & 3;
    int g = lane >> 2, c = lane & 3;
    int row0 = blockIdx.y * 128, col0 = blockIdx.x * 128;

    int ar = tid >> 1;                  // A row 0..127
    int ak = (tid & 1) << 3;            // half-offset 0 or 8 within 16-col k-tile
    float dv = dinv[row0 + ar];
    int bkr = tid >> 4;
    int bc0 = (tid & 15) << 3;

    const int KT = K / 16;

    float d[4][4][4];
    #pragma unroll
    for (int mt = 0; mt < 4; mt++)
        #pragma unroll
        for (int nt = 0; nt < 4; nt++)
            #pragma unroll
            for (int r = 0; r < 4; r++) d[mt][nt][r] = 0.0f;

    // A k-tile loader: 8 halves (16B) per thread
    auto stage_a = [&](int buf, uint4 raw) {
        uint32_t w[4] = {raw.x, raw.y, raw.z, raw.w};
        #pragma unroll
        for (int j = 0; j < 4; j++) {
            float2 f = __half22float2(bits_h2(w[j]));
            Ah[buf][ar][ak + 2 * j]     = f2tf32f(dv * f.x);
            Ah[buf][ar][ak + 2 * j + 1] = f2tf32f(dv * f.y);
        }
    };
    auto stage_b = [&](int buf, float4 b0, float4 b1) {
        Bh[buf][bkr][bc0 + 0] = f2tf32f(b0.x); Bh[buf][bkr][bc0 + 1] = f2tf32f(b0.y);
        Bh[buf][bkr][bc0 + 2] = f2tf32f(b0.z); Bh[buf][bkr][bc0 + 3] = f2tf32f(b0.w);
        Bh[buf][bkr][bc0 + 4] = f2tf32f(b1.x); Bh[buf][bkr][bc0 + 5] = f2tf32f(b1.y);
        Bh[buf][bkr][bc0 + 6] = f2tf32f(b1.z); Bh[buf][bkr][bc0 + 7] = f2tf32f(b1.w);
    };

    {
        uint4 raw = *reinterpret_cast<const uint4*>(A + (size_t)(row0 + ar) * K + ak);
        stage_a(0, raw);
        float4 b0 = *reinterpret_cast<const float4*>(Wt + (size_t)bkr * N + col0 + bc0);
        float4 b1 = *reinterpret_cast<const float4*>(Wt + (size_t)bkr * N + col0 + bc0 + 4);
        stage_b(0, b0, b1);
    }
    __syncthreads();

    for (int kt = 0; kt < KT; kt++) {
        int cur = kt & 1, nxt = cur ^ 1;
        uint4 raw; float4 b0, b1;
        bool more = (kt + 1 < KT);
        if (more) {
            int koff = (kt + 1) * 16;
            raw = *reinterpret_cast<const uint4*>(A + (size_t)(row0 + ar) * K + koff + ak);
            b0 = *reinterpret_cast<const float4*>(Wt + (size_t)(koff + bkr) * N + col0 + bc0);
            b1 = *reinterpret_cast<const float4*>(Wt + (size_t)(koff + bkr) * N + col0 + bc0 + 4);
        }

        #pragma unroll
        for (int ks = 0; ks < 2; ks++) {
            int k0 = ks << 3;
            uint32_t af[4][4];
            #pragma unroll
            for (int mt = 0; mt < 4; mt++) {
                int rm = wm * 64 + mt * 16;
                af[mt][0] = __float_as_uint(Ah[cur][rm + g][k0 + c]);
                af[mt][1] = __float_as_uint(Ah[cur][rm + g + 8][k0 + c]);
                af[mt][2] = __float_as_uint(Ah[cur][rm + g][k0 + c + 4]);
                af[mt][3] = __float_as_uint(Ah[cur][rm + g + 8][k0 + c + 4]);
            }
            uint32_t bf[4][2];
            #pragma unroll
            for (int nt = 0; nt < 4; nt++) {
                int nb = wn * 32 + nt * 8;
                bf[nt][0] = __float_as_uint(Bh[cur][k0 + c][nb + g]);
                bf[nt][1] = __float_as_uint(Bh[cur][k0 + c + 4][nb + g]);
            }
            #pragma unroll
            for (int mt = 0; mt < 4; mt++)
                #pragma unroll
                for (int nt = 0; nt < 4; nt++)
                    mma_tf32(d[mt][nt], af[mt][0], af[mt][1], af[mt][2], af[mt][3],
                             bf[nt][0], bf[nt][1]);
        }

        if (more) { stage_a(nxt, raw); stage_b(nxt, b0, b1); }
        __syncthreads();
    }

    float bv[4][2];
    #pragma unroll
    for (int nt = 0; nt < 4; nt++) {
        int cc = col0 + wn * 32 + nt * 8 + (c << 1);
        bv[nt][0] = bias[cc];
        bv[nt][1] = bias[cc + 1];
    }

    if (!DO_MAX) {
        #pragma unroll
        for (int mt = 0; mt < 4; mt++) {
            int rbase = row0 + wm * 64 + mt * 16;
            #pragma unroll
            for (int half = 0; half < 2; half++) {
                int r = rbase + g + half * 8;
                float dv2 = dinv[r];
                #pragma unroll
                for (int nt = 0; nt < 4; nt++) {
                    int cc = col0 + wn * 32 + nt * 8 + (c << 1);
                    __half2 o = __floats2half2_rn(
                        dv2 * selu_f(d[mt][nt][half * 2 + 0] + bv[nt][0]),
                        dv2 * selu_f(d[mt][nt][half * 2 + 1] + bv[nt][1]));
                    size_t addr = (size_t)r * N + cc;
                    *reinterpret_cast<__half2*>(O1 + addr) = o;
                    *reinterpret_cast<__half2*>(O2 + addr) = o;
                }
            }
        }
    } else {
        float mv[4][2];
        #pragma unroll
        for (int nt = 0; nt < 4; nt++) { mv[nt][0] = mv[nt][1] = __int_as_float(0xff800000); }
        #pragma unroll
        for (int mt = 0; mt < 4; mt++)
            #pragma unroll
            for (int nt = 0; nt < 4; nt++) {
                mv[nt][0] = fmaxf(mv[nt][0], fmaxf(selu_f(d[mt][nt][0] + bv[nt][0]),
                                                   selu_f(d[mt][nt][2] + bv[nt][0])));
                mv[nt][1] = fmaxf(mv[nt][1], fmaxf(selu_f(d[mt][nt][1] + bv[nt][1]),
                                                   selu_f(d[mt][nt][3] + bv[nt][1])));
            }
        #pragma unroll
        for (int off = 4; off <= 16; off <<= 1)
            #pragma unroll
            for (int nt = 0; nt < 4; nt++) {
                mv[nt][0] = fmaxf(mv[nt][0], __shfl_xor_sync(0xffffffffu, mv[nt][0], off));
                mv[nt][1] = fmaxf(mv[nt][1], __shfl_xor_sync(0xffffffffu, mv[nt][1], off));
            }
        if (lane < 4) {
            int b = row0 >> 12;
            #pragma unroll
            for (int nt = 0; nt < 4; nt++) {
                int cc = col0 + wn * 32 + nt * 8 + (lane << 1);
                atomicMaxF(&lat[b * C2 + cc], mv[nt][0]);
                atomicMaxF(&lat[b * C2 + cc + 1], mv[nt][1]);
            }
        }
    }
}

// ---------------- lat2 = selu(lat @ w_e2 + b_e2) ----------------
__global__ void e2_kernel(const float* __restrict__ lat, const float* __restrict__ w,
                          const float* __restrict__ bias, float* __restrict__ lat2) {
    __shared__ float row[C2];
    int c = threadIdx.x;
    row[c] = lat[blockIdx.x * C2 + c];
    __syncthreads();
    float acc = bias[c];
    #pragma unroll 8
    for (int k = 0; k < C2; k++) acc = fmaf(row[k], w[k * C2 + c], acc);
    lat2[blockIdx.x * C2 + c] = selu_f(acc);
}

// ---------------- decoder ----------------
__global__ void base_kernel(const float* __restrict__ lat2,
                            const float* __restrict__ w_d1,
                            const float* __restrict__ w_d2,
                            float* __restrict__ base) {
    int o = blockIdx.x;
    int b = o / 6, t = o % 6, j = t % 3;
    const float* w = (t < 3) ? w_d1 : w_d2;
    int lane = threadIdx.x;
    float s = 0.0f;
    for (int c = lane; c < C2; c += 32) s += lat2[b * C2 + c] * w[c * 3 + j];
    #pragma unroll
    for (int off = 16; off > 0; off >>= 1) s += __shfl_xor_sync(0xffffffffu, s, off);
    if (lane == 0) base[b * 6 + t] = s;
}

__global__ void final_kernel(const float* __restrict__ base,
                             const float* __restrict__ w_d1, const float* __restrict__ b_d1,
                             const float* __restrict__ w_d2, const float* __restrict__ b_d2,
                             float* __restrict__ out) {
    int idx = blockIdx.x * blockDim.x + threadIdx.x;
    int b = idx >> 12, n = idx & 4095;
    int ix = n / 46, iy = n % 46;
    float y0 = 1.0f + ix * (119.0f / 90.0f);
    float y1 = 1.0f + iy * (59.0f / 45.0f);
    float kk[3];
    #pragma unroll
    for (int j = 0; j < 3; j++)
        kk[j] = selu_f(base[b * 6 + j] + y0 * w_d1[512 * 3 + j] + y1 * w_d1[513 * 3 + j] + b_d1[j]);
    #pragma unroll
    for (int j = 0; j < 3; j++) {
        float v = base[b * 6 + 3 + j]
                + kk[0] * w_d2[512 * 3 + j]
                + kk[1] * w_d2[513 * 3 + j]
                + kk[2] * w_d2[514 * 3 + j]
                + b_d2[j];
        out[(size_t)idx * 3 + j] = selu_f(v);
    }
}

// ---------------- launch ----------------
extern "C" void kernel_launch(void* const* d_in, const int* in_sizes, int n_in,
                              void* d_out, int out_size) {
    const float* x    = (const float*)d_in[0];
    const int*   knn  = (const int*)  d_in[1];
    const float* w_e1 = (const float*)d_in[2];
    const float* b_e1 = (const float*)d_in[3];
    const float* w_g1 = (const float*)d_in[4];
    const float* b_g1 = (const float*)d_in[5];
    const float* w_g2 = (const float*)d_in[6];
    const float* b_g2 = (const float*)d_in[7];
    const float* w_e2 = (const float*)d_in[8];
    const float* b_e2 = (const float*)d_in[9];
    const float* w_d1 = (const float*)d_in[10];
    const float* b_d1 = (const float*)d_in[11];
    const float* w_d2 = (const float*)d_in[12];
    const float* b_d2 = (const float*)d_in[13];
    float* out = (float*)d_out;
    const int* src = knn;
    const int* dst = knn + NEDGE;

    __half *p_h0, *p_agg0, *p_h1, *p_agg1;
    float *p_lat, *p_lat2, *p_base, *p_dinv;
    cudaGetSymbolAddress((void**)&p_h0,   g_h0);
    cudaGetSymbolAddress((void**)&p_agg0, g_agg0);
    cudaGetSymbolAddress((void**)&p_h1,   g_h1);
    cudaGetSymbolAddress((void**)&p_agg1, g_agg1);
    cudaGetSymbolAddress((void**)&p_lat,  g_lat);
    cudaGetSymbolAddress((void**)&p_lat2, g_lat2);
    cudaGetSymbolAddress((void**)&p_base, g_base);
    cudaGetSymbolAddress((void**)&p_dinv, g_dinv);

    init_kernel<<<BN / 256, 256>>>();
    deg_kernel<<<NEDGE / 256, 256>>>(dst);
    dinv_kernel<<<BN / 256, 256>>>();
    cov_e1_kernel<<<BN / 32, 128>>>(x, w_e1, b_e1);

    // GCN layer 1: 64 halves/row = 8 chunks of 8 halves
    edge_kernel<3><<<(NEDGE * 8) / 256, 256>>>(src, dst, p_h0, p_agg0);
    gemm_tf32_kernel<C1, C0, false><<<dim3(C1 / 128, BN / 128), 256>>>(
        p_agg0, p_dinv, w_g1, b_g1, p_h1, p_agg1, nullptr);

    // GCN layer 2 + fused max-pool: 128 halves/row = 16 chunks of 8 halves
    edge_kernel<4><<<(NEDGE * 16) / 256, 256>>>(src, dst, p_h1, p_agg1);
    gemm_tf32_kernel<C2, C1, true><<<dim3(C2 / 128, BN / 128), 256>>>(
        p_agg1, p_dinv, w_g2, b_g2, nullptr, nullptr, p_lat);

    e2_kernel<<<NB, C2>>>(p_lat, w_e2, b_e2, p_lat2);
    base_kernel<<<NB * 6, 32>>>(p_lat2, w_d1, w_d2, p_base);
    final_kernel<<<BN / 256, 256>>>(p_base, w_d1, b_d1, w_d2, b_d2, out);
}